// round 2
// baseline (speedup 1.0000x reference)
#include <cuda_runtime.h>
#include <math.h>

#define HH 134
#define WW 20
#define HW 2680
#define CC 64
#define BB 128
#define RT 34          // rows per tile
#define NT 4           // row tiles
#define GPC 335        // 8-groups per channel plane

// ---- scratch (static device globals) ----
__device__ float d_h0[(size_t)BB * CC * HW];   // 87.8 MB
__device__ float d_psum[NT * BB * CC];
__device__ float d_pmax[NT * BB * CC];
__device__ float d_ca[BB * CC];
__device__ float d_sa[BB * HW];
__device__ float d_g[BB * 16];
__device__ float d_psc[8 * BB * 32];           // routing partials per cgroup

// ---------------------------------------------------------------------------
// K1: 3x3 conv (1->64) + ReLU, tiled (8 channel-groups x 4 row-tiles, BB)
// writes h0; per (tile,b,c) sum/max partials (deterministic, no atomics)
// ---------------------------------------------------------------------------
__global__ void k_conv(const float* __restrict__ x,
                       const float* __restrict__ cw,
                       const float* __restrict__ cb) {
    const int cg = blockIdx.x >> 2, tile = blockIdx.x & 3, b = blockIdx.y;
    const int tid = threadIdx.x;
    const int r0 = tile * RT, nr = min(RT, HH - r0);
    const int lr0 = max(r0 - 1, 0), lr1 = min(r0 + nr + 1, HH), nl = lr1 - lr0;

    __shared__ float xs[(RT + 2) * WW];
    __shared__ float wsh[80];
    __shared__ float red[8 * 16];

    for (int i = tid; i < nl * WW; i += 256) xs[i] = x[(size_t)b * HW + lr0 * WW + i];
    if (tid < 72) wsh[tid] = cw[cg * 72 + tid];
    if (tid >= 72 && tid < 80) wsh[tid] = cb[cg * 8 + tid - 72];
    __syncthreads();

    float wr[8][9], bsr[8];
#pragma unroll
    for (int c = 0; c < 8; c++) {
#pragma unroll
        for (int i = 0; i < 9; i++) wr[c][i] = wsh[c * 9 + i];
        bsr[c] = wsh[72 + c];
    }

    float sum[8], mx[8];
#pragma unroll
    for (int c = 0; c < 8; c++) { sum[c] = 0.f; mx[c] = 0.f; }  // h>=0 after relu

    float* outb = d_h0 + ((size_t)b * CC + cg * 8) * HW;
    for (int p = tid; p < nr * WW; p += 256) {
        const int hh = r0 + p / WW, ww = p - (p / WW) * WW;
        float win[9];
#pragma unroll
        for (int kh = 0; kh < 3; kh++) {
            const int ih = hh + kh - 1;
            const bool vr = (unsigned)ih < HH;
            const int lrow = ih - lr0;
#pragma unroll
            for (int kw = 0; kw < 3; kw++) {
                const int iw = ww + kw - 1;
                win[kh * 3 + kw] = (vr && (unsigned)iw < WW) ? xs[lrow * WW + iw] : 0.f;
            }
        }
#pragma unroll
        for (int c = 0; c < 8; c++) {
            float acc = bsr[c];
#pragma unroll
            for (int i = 0; i < 9; i++) acc += win[i] * wr[c][i];
            acc = fmaxf(acc, 0.f);
            outb[(size_t)c * HW + hh * WW + ww] = acc;
            sum[c] += acc;
            mx[c] = fmaxf(mx[c], acc);
        }
    }

    const int warp = tid >> 5, lane = tid & 31;
#pragma unroll
    for (int c = 0; c < 8; c++) {
#pragma unroll
        for (int off = 16; off; off >>= 1) {
            sum[c] += __shfl_down_sync(0xffffffffu, sum[c], off);
            mx[c] = fmaxf(mx[c], __shfl_down_sync(0xffffffffu, mx[c], off));
        }
    }
    if (lane == 0) {
#pragma unroll
        for (int c = 0; c < 8; c++) { red[warp * 16 + c] = sum[c]; red[warp * 16 + 8 + c] = mx[c]; }
    }
    __syncthreads();
    if (tid < 8) {
        float s = 0.f;
#pragma unroll
        for (int w = 0; w < 8; w++) s += red[w * 16 + tid];
        d_psum[(tile * BB + b) * CC + cg * 8 + tid] = s;
    } else if (tid < 16) {
        float m = 0.f;
#pragma unroll
        for (int w = 0; w < 8; w++) m = fmaxf(m, red[w * 16 + tid]);
        d_pmax[(tile * BB + b) * CC + cg * 8 + tid - 8] = m;
    }
}

// ---------------------------------------------------------------------------
// K2: channel attention MLP (+ zero g). grid BB, 64 threads
// ---------------------------------------------------------------------------
__global__ void k_ca(const float* __restrict__ w1, const float* __restrict__ w2) {
    __shared__ float avg[CC], mx[CC], hid[8];
    const int b = blockIdx.x, tid = threadIdx.x;
    float s = 0.f, m = 0.f;
#pragma unroll
    for (int t = 0; t < NT; t++) {
        s += d_psum[(t * BB + b) * CC + tid];
        m = fmaxf(m, d_pmax[(t * BB + b) * CC + tid]);
    }
    avg[tid] = s * (1.f / (float)HW);
    mx[tid] = m;
    if (tid < 16) d_g[b * 16 + tid] = 0.f;
    __syncthreads();
    if (tid < 8) {
        const int i = tid & 3;
        const float* v = (tid < 4) ? avg : mx;
        float a = 0.f;
        for (int c = 0; c < CC; c++) a += v[c] * w1[i * CC + c];
        hid[tid] = fmaxf(a, 0.f);
    }
    __syncthreads();
    float o = 0.f;
#pragma unroll
    for (int i = 0; i < 4; i++) o += (hid[i] + hid[4 + i]) * w2[tid * 4 + i];
    d_ca[b * CC + tid] = 1.f / (1.f + __expf(-o));
}

// ---------------------------------------------------------------------------
// K3: spatial attention, row-tiled with 3-row halo recompute. grid (NT,BB)x512
// ---------------------------------------------------------------------------
__global__ void k_spatial(const float* __restrict__ sw) {
    __shared__ float spm[(RT + 6) * WW], spx[(RT + 6) * WW];
    __shared__ float cas[CC], ws[98];
    const int tile = blockIdx.x, b = blockIdx.y, tid = threadIdx.x;
    const int r0 = tile * RT, nr = min(RT, HH - r0);
    const int lr0 = max(r0 - 3, 0), lr1 = min(r0 + nr + 3, HH), nl = lr1 - lr0;

    if (tid < CC) cas[tid] = d_ca[b * CC + tid];
    if (tid >= 128 && tid < 128 + 98) ws[tid - 128] = sw[tid - 128];
    __syncthreads();

    const float* hp = d_h0 + (size_t)b * CC * HW;
    for (int p = tid; p < nl * WW; p += 512) {
        const int gp = lr0 * WW + p;
        float s = 0.f, m = -1e30f;
#pragma unroll 8
        for (int c = 0; c < CC; c++) {
            const float v = hp[(size_t)c * HW + gp] * cas[c];
            s += v;
            m = fmaxf(m, v);
        }
        spm[p] = s * (1.f / (float)CC);
        spx[p] = m;
    }
    __syncthreads();
    for (int p = tid; p < nr * WW; p += 512) {
        const int hh = r0 + p / WW, ww = p - (p / WW) * WW;
        float acc = 0.f;
#pragma unroll
        for (int kh = 0; kh < 7; kh++) {
            const int ih = hh + kh - 3;
            if ((unsigned)ih >= HH) continue;
            const int lrow = ih - lr0;
#pragma unroll
            for (int kw = 0; kw < 7; kw++) {
                const int iw = ww + kw - 3;
                if ((unsigned)iw >= WW) continue;
                const int q = lrow * WW + iw;
                acc += spm[q] * ws[kh * 7 + kw] + spx[q] * ws[49 + kh * 7 + kw];
            }
        }
        d_sa[b * HW + hh * WW + ww] = 1.f / (1.f + __expf(-acc));
    }
}

// ---------------------------------------------------------------------------
// R: one routing streaming pass, split by channel-group. grid (8,BB) x 256
// writes deterministic partials to d_psc (a0 = sum c0*u, as = sum u)
// ---------------------------------------------------------------------------
__global__ void k_route() {
    __shared__ float sas[HW];
    __shared__ float cavs[8];
    __shared__ float gs[16];
    __shared__ float red[8][32];
    const int cg = blockIdx.x, b = blockIdx.y, tid = threadIdx.x;
    const int warp = tid >> 5, lane = tid & 31;

    for (int p = tid; p < HW; p += 256) sas[p] = d_sa[b * HW + p];
    if (tid < 8) cavs[tid] = d_ca[b * CC + cg * 8 + tid];
    if (tid >= 32 && tid < 48) gs[tid - 32] = d_g[b * 16 + tid - 32];
    __syncthreads();

    float gd[8];
#pragma unroll
    for (int k = 0; k < 8; k++) gd[k] = gs[k] - gs[8 + k];

    float a0[8], as[8];
#pragma unroll
    for (int k = 0; k < 8; k++) { a0[k] = 0.f; as[k] = 0.f; }

    const float* hp = d_h0 + ((size_t)b * CC + cg * 8) * HW;
    for (int n = tid; n < HW; n += 256) {
        const int cl = n / GPC;
        const int pos = (n - cl * GPC) * 8;
        const float4* up = (const float4*)(hp + (size_t)n * 8);
        const float4 q0 = up[0];
        const float4 q1 = up[1];
        float t[8];
        t[0] = q0.x * sas[pos + 0];
        t[1] = q0.y * sas[pos + 1];
        t[2] = q0.z * sas[pos + 2];
        t[3] = q0.w * sas[pos + 3];
        t[4] = q1.x * sas[pos + 4];
        t[5] = q1.y * sas[pos + 5];
        t[6] = q1.z * sas[pos + 6];
        t[7] = q1.w * sas[pos + 7];
        const float cv = cavs[cl];
        float d = 0.f;
#pragma unroll
        for (int k = 0; k < 8; k++) d += t[k] * gd[k];
        const float c0 = cv / (1.f + __expf(-d * cv));
#pragma unroll
        for (int k = 0; k < 8; k++) { a0[k] += c0 * t[k]; as[k] += cv * t[k]; }
    }

#pragma unroll
    for (int k = 0; k < 8; k++) {
#pragma unroll
        for (int off = 16; off; off >>= 1) {
            a0[k] += __shfl_down_sync(0xffffffffu, a0[k], off);
            as[k] += __shfl_down_sync(0xffffffffu, as[k], off);
        }
    }
    if (lane == 0) {
#pragma unroll
        for (int k = 0; k < 8; k++) { red[warp][k] = a0[k]; red[warp][16 + k] = as[k]; }
    }
    __syncthreads();
    if (tid < 32) {
        float s = 0.f;
#pragma unroll
        for (int w = 0; w < 8; w++) s += red[w][tid];
        d_psc[((size_t)cg * BB + b) * 32 + tid] = s;
    }
}

// ---------------------------------------------------------------------------
// U: per-batch routing update (reduce partials, squash, update g / lengths)
// grid BB, 32 threads (one warp)
// ---------------------------------------------------------------------------
template <int FINAL>
__global__ void k_update(const float* __restrict__ W, float* __restrict__ out) {
    __shared__ float sh[32], ss[32], vs[32];
    const int b = blockIdx.x, tid = threadIdx.x;

    float s = 0.f;
#pragma unroll
    for (int cg = 0; cg < 8; cg++) s += d_psc[((size_t)cg * BB + b) * 32 + tid];
    sh[tid] = s;
    __syncwarp();

    const int j = tid >> 4;
    float acc = 0.f;
#pragma unroll
    for (int k = 0; k < 8; k++) {
        const float sck = (j == 0) ? sh[k] : (sh[16 + k] - sh[k]);
        acc += sck * W[k * 32 + tid];
    }
    ss[tid] = acc;
    __syncwarp();

    float s2 = 1e-8f;
#pragma unroll
    for (int dd = 0; dd < 16; dd++) { const float t = ss[j * 16 + dd]; s2 += t * t; }
    const float v = (sqrtf(s2) / (1.f + s2)) * acc;
    vs[tid] = v;
    __syncwarp();

    if (FINAL) {
        if (tid < 2) {
            float l2 = 1e-8f;
#pragma unroll
            for (int dd = 0; dd < 16; dd++) { const float t = vs[tid * 16 + dd]; l2 += t * t; }
            out[b * 2 + tid] = sqrtf(l2);
        }
    } else {
        if (tid < 16) {
            const int jj = tid >> 3, k = tid & 7;
            float a = 0.f;
#pragma unroll
            for (int dd = 0; dd < 16; dd++) a += vs[jj * 16 + dd] * W[k * 32 + jj * 16 + dd];
            d_g[b * 16 + tid] += a;
        }
    }
}

// ---------------------------------------------------------------------------
extern "C" void kernel_launch(void* const* d_in, const int* in_sizes, int n_in,
                              void* d_out, int out_size) {
    const float* x      = (const float*)d_in[0];
    const float* conv_w = (const float*)d_in[1];
    const float* conv_b = (const float*)d_in[2];
    const float* ca_w1  = (const float*)d_in[3];
    const float* ca_w2  = (const float*)d_in[4];
    const float* sa_w   = (const float*)d_in[5];
    const float* caps_W = (const float*)d_in[6];
    float* out = (float*)d_out;

    k_conv<<<dim3(32, BB), 256>>>(x, conv_w, conv_b);
    k_ca<<<BB, 64>>>(ca_w1, ca_w2);
    k_spatial<<<dim3(NT, BB), 512>>>(sa_w);

    k_route<<<dim3(8, BB), 256>>>();
    k_update<0><<<BB, 32>>>(caps_W, out);
    k_route<<<dim3(8, BB), 256>>>();
    k_update<0><<<BB, 32>>>(caps_W, out);
    k_route<<<dim3(8, BB), 256>>>();
    k_update<1><<<BB, 32>>>(caps_W, out);
}

// round 3
// speedup vs baseline: 1.3664x; 1.3664x over previous
#include <cuda_runtime.h>
#include <cuda_fp16.h>
#include <math.h>

#define HH 134
#define WW 20
#define HW 2680
#define CC 64
#define BB 128
#define NIN 21440        // CC*HW/8 groups per batch
#define NT_S 4
#define RT_S 34
#define NTF 8
#define RTF 17

// ---- scratch (static device globals) ----
__device__ __half d_u[(size_t)BB * CC * HW];   // fused features, fp16, 43.9 MB
__device__ float d_psum[NT_S * BB * CC];
__device__ float d_pmax[NT_S * BB * CC];
__device__ float d_ca[BB * CC];
__device__ float d_pu[NTF * BB * 8];           // per-tile partials of Sum_n u[k]
__device__ float d_S[BB * 8];                  // Sum_n u[k]
__device__ float d_psc[8 * BB * 8];            // route partials: sum c0*u[k]
__device__ float d_g[BB * 16];

// ---------------------------------------------------------------------------
// K1: conv+relu stats only (sum/max per (b,c)), h discarded.
// grid (32, BB): blockIdx.x = cg*4 + tile. 256 threads.
// ---------------------------------------------------------------------------
__global__ void k_stats(const float* __restrict__ x,
                        const float* __restrict__ cw,
                        const float* __restrict__ cb) {
    const int cg = blockIdx.x >> 2, tile = blockIdx.x & 3, b = blockIdx.y;
    const int tid = threadIdx.x;
    const int r0 = tile * RT_S, nr = min(RT_S, HH - r0);
    const int lr0 = max(r0 - 1, 0), lr1 = min(r0 + nr + 1, HH), nl = lr1 - lr0;

    __shared__ float xs[(RT_S + 2) * WW];
    __shared__ float wsh[80];
    __shared__ float red[8 * 16];

    for (int i = tid; i < nl * WW; i += 256) xs[i] = x[(size_t)b * HW + lr0 * WW + i];
    if (tid < 72) wsh[tid] = cw[cg * 72 + tid];
    if (tid >= 72 && tid < 80) wsh[tid] = cb[cg * 8 + tid - 72];
    __syncthreads();

    float wr[8][9], bsr[8];
#pragma unroll
    for (int c = 0; c < 8; c++) {
#pragma unroll
        for (int i = 0; i < 9; i++) wr[c][i] = wsh[c * 9 + i];
        bsr[c] = wsh[72 + c];
    }
    float sum[8], mx[8];
#pragma unroll
    for (int c = 0; c < 8; c++) { sum[c] = 0.f; mx[c] = 0.f; }

    for (int p = tid; p < nr * WW; p += 256) {
        const int hh = r0 + p / WW, ww = p - (p / WW) * WW;
        float win[9];
#pragma unroll
        for (int kh = 0; kh < 3; kh++) {
            const int ih = hh + kh - 1;
            const bool vr = (unsigned)ih < HH;
            const int lrow = ih - lr0;
#pragma unroll
            for (int kw = 0; kw < 3; kw++) {
                const int iw = ww + kw - 1;
                win[kh * 3 + kw] = (vr && (unsigned)iw < WW) ? xs[lrow * WW + iw] : 0.f;
            }
        }
#pragma unroll
        for (int c = 0; c < 8; c++) {
            float acc = bsr[c];
#pragma unroll
            for (int i = 0; i < 9; i++) acc += win[i] * wr[c][i];
            acc = fmaxf(acc, 0.f);
            sum[c] += acc;
            mx[c] = fmaxf(mx[c], acc);
        }
    }
    const int warp = tid >> 5, lane = tid & 31;
#pragma unroll
    for (int c = 0; c < 8; c++) {
#pragma unroll
        for (int off = 16; off; off >>= 1) {
            sum[c] += __shfl_down_sync(0xffffffffu, sum[c], off);
            mx[c] = fmaxf(mx[c], __shfl_down_sync(0xffffffffu, mx[c], off));
        }
    }
    if (lane == 0) {
#pragma unroll
        for (int c = 0; c < 8; c++) { red[warp * 16 + c] = sum[c]; red[warp * 16 + 8 + c] = mx[c]; }
    }
    __syncthreads();
    if (tid < 8) {
        float s = 0.f;
#pragma unroll
        for (int w = 0; w < 8; w++) s += red[w * 16 + tid];
        d_psum[(tile * BB + b) * CC + cg * 8 + tid] = s;
    } else if (tid < 16) {
        float m = 0.f;
#pragma unroll
        for (int w = 0; w < 8; w++) m = fmaxf(m, red[w * 16 + tid - 8]);
        d_pmax[(tile * BB + b) * CC + cg * 8 + tid - 8] = m;
    }
}

// ---------------------------------------------------------------------------
// K2: channel attention MLP. grid BB, 64 threads.
// ---------------------------------------------------------------------------
__global__ void k_ca(const float* __restrict__ w1, const float* __restrict__ w2) {
    __shared__ float avg[CC], mx[CC], hid[8];
    const int b = blockIdx.x, tid = threadIdx.x;
    float s = 0.f, m = 0.f;
#pragma unroll
    for (int t = 0; t < NT_S; t++) {
        s += d_psum[(t * BB + b) * CC + tid];
        m = fmaxf(m, d_pmax[(t * BB + b) * CC + tid]);
    }
    avg[tid] = s * (1.f / (float)HW);
    mx[tid] = m;
    __syncthreads();
    if (tid < 8) {
        const int i = tid & 3;
        const float* v = (tid < 4) ? avg : mx;
        float a = 0.f;
        for (int c = 0; c < CC; c++) a += v[c] * w1[i * CC + c];
        hid[tid] = fmaxf(a, 0.f);
    }
    __syncthreads();
    float o = 0.f;
#pragma unroll
    for (int i = 0; i < 4; i++) o += (hid[i] + hid[4 + i]) * w2[tid * 4 + i];
    d_ca[b * CC + tid] = 1.f / (1.f + __expf(-o));
}

// ---------------------------------------------------------------------------
// K3: fused spatial attention + u production (fp16) + Sum_u partials.
// Recomputes conv twice (no h0 buffer). grid (NTF, BB), 256 threads.
// ---------------------------------------------------------------------------
__global__ void k_fuse(const float* __restrict__ x,
                       const float* __restrict__ cw,
                       const float* __restrict__ cb,
                       const float* __restrict__ sw) {
    __shared__ __align__(16) float wsh[CC * 12];
    __shared__ float cbs[CC], cas[CC], ws[98];
    __shared__ float xs[27 * WW];
    __shared__ float spm[23 * WW], spx[23 * WW];
    __shared__ float sa_s[RTF * WW];
    __shared__ float red[8][8];

    const int tile = blockIdx.x, b = blockIdx.y, tid = threadIdx.x;
    const int r0 = tile * RTF, nr = min(RTF, HH - r0);
    const int hs0 = max(r0 - 3, 0), hs1 = min(r0 + nr + 3, HH), nhs = hs1 - hs0;
    const int lx0 = max(hs0 - 1, 0), lx1 = min(hs1 + 1, HH), nlx = lx1 - lx0;

    for (int i = tid; i < CC * 12; i += 256) {
        const int c = i / 12, q = i - c * 12;
        wsh[i] = (q < 9) ? cw[c * 9 + q] : 0.f;
    }
    if (tid < CC) { cbs[tid] = cb[tid]; cas[tid] = d_ca[b * CC + tid]; }
    if (tid >= 64 && tid < 64 + 98) ws[tid - 64] = sw[tid - 64];
    for (int i = tid; i < nlx * WW; i += 256) xs[i] = x[(size_t)b * HW + lx0 * WW + i];
    __syncthreads();

    // ---- pass A: spm/spx over halo rows (conv recompute #1) ----
    {
        const int pairs = nhs * 10;
        if (tid < pairs) {
            const int row = hs0 + tid / 10, col2 = (tid - (tid / 10) * 10) * 2;
            float win[3][4];
#pragma unroll
            for (int r = 0; r < 3; r++) {
                const int ih = row - 1 + r;
                const bool vr = (ih >= lx0) && (ih < lx1);
                const int lrow = ih - lx0;
#pragma unroll
                for (int q = 0; q < 4; q++) {
                    const int iw = col2 - 1 + q;
                    win[r][q] = (vr && (unsigned)iw < WW) ? xs[lrow * WW + iw] : 0.f;
                }
            }
            float s0 = 0.f, s1 = 0.f, m0 = -1e30f, m1 = -1e30f;
#pragma unroll 4
            for (int c = 0; c < CC; c++) {
                const float4 wa = *(const float4*)&wsh[c * 12];
                const float4 wb = *(const float4*)&wsh[c * 12 + 4];
                const float w8 = wsh[c * 12 + 8];
                const float bias = cbs[c];
                float h0 = bias + wa.x * win[0][0] + wa.y * win[0][1] + wa.z * win[0][2]
                                + wa.w * win[1][0] + wb.x * win[1][1] + wb.y * win[1][2]
                                + wb.z * win[2][0] + wb.w * win[2][1] + w8 * win[2][2];
                float h1 = bias + wa.x * win[0][1] + wa.y * win[0][2] + wa.z * win[0][3]
                                + wa.w * win[1][1] + wb.x * win[1][2] + wb.y * win[1][3]
                                + wb.z * win[2][1] + wb.w * win[2][2] + w8 * win[2][3];
                h0 = fmaxf(h0, 0.f) * cas[c];
                h1 = fmaxf(h1, 0.f) * cas[c];
                s0 += h0; s1 += h1;
                m0 = fmaxf(m0, h0); m1 = fmaxf(m1, h1);
            }
            const int lp = (row - hs0) * WW + col2;
            spm[lp] = s0 * (1.f / (float)CC);
            spm[lp + 1] = s1 * (1.f / (float)CC);
            spx[lp] = m0;
            spx[lp + 1] = m1;
        }
    }
    __syncthreads();

    // ---- pass B: 7x7 conv -> sa; accumulate Sum_u[k] partials ----
    float ps[8];
#pragma unroll
    for (int k = 0; k < 8; k++) ps[k] = 0.f;
    for (int p = tid; p < nr * WW; p += 256) {
        const int hh = r0 + p / WW, ww = p - (p / WW) * WW;
        float acc = 0.f;
#pragma unroll
        for (int kh = 0; kh < 7; kh++) {
            const int ih = hh + kh - 3;
            if ((unsigned)ih >= HH) continue;
            const int lrow = ih - hs0;
#pragma unroll
            for (int kw = 0; kw < 7; kw++) {
                const int iw = ww + kw - 3;
                if ((unsigned)iw >= WW) continue;
                const int q = lrow * WW + iw;
                acc += spm[q] * ws[kh * 7 + kw] + spx[q] * ws[49 + kh * 7 + kw];
            }
        }
        const float sa = 1.f / (1.f + __expf(-acc));
        sa_s[p] = sa;
        const int k = (r0 * WW + p) & 7;
        ps[k] += (float)CC * spm[(hh - hs0) * WW + ww] * sa;
    }
    const int warp = tid >> 5, lane = tid & 31;
#pragma unroll
    for (int k = 0; k < 8; k++) {
#pragma unroll
        for (int off = 16; off; off >>= 1)
            ps[k] += __shfl_down_sync(0xffffffffu, ps[k], off);
    }
    if (lane == 0) {
#pragma unroll
        for (int k = 0; k < 8; k++) red[warp][k] = ps[k];
    }
    __syncthreads();
    if (tid < 8) {
        float s = 0.f;
#pragma unroll
        for (int w = 0; w < 8; w++) s += red[w][tid];
        d_pu[(tile * BB + b) * 8 + tid] = s;
    }

    // ---- pass C: write u = h*ca*sa in fp16 (conv recompute #2) ----
    {
        const int pairs = nr * 10;
        if (tid < pairs) {
            const int lrow = tid / 10, col2 = (tid - lrow * 10) * 2;
            const int row = r0 + lrow;
            float win[3][4];
#pragma unroll
            for (int r = 0; r < 3; r++) {
                const int ih = row - 1 + r;
                const bool vr = (ih >= lx0) && (ih < lx1);
                const int lr = ih - lx0;
#pragma unroll
                for (int q = 0; q < 4; q++) {
                    const int iw = col2 - 1 + q;
                    win[r][q] = (vr && (unsigned)iw < WW) ? xs[lr * WW + iw] : 0.f;
                }
            }
            const float sa0 = sa_s[lrow * WW + col2];
            const float sa1 = sa_s[lrow * WW + col2 + 1];
            __half* ub = d_u + (size_t)b * CC * HW + row * WW + col2;
#pragma unroll 4
            for (int c = 0; c < CC; c++) {
                const float4 wa = *(const float4*)&wsh[c * 12];
                const float4 wb = *(const float4*)&wsh[c * 12 + 4];
                const float w8 = wsh[c * 12 + 8];
                const float bias = cbs[c];
                float h0 = bias + wa.x * win[0][0] + wa.y * win[0][1] + wa.z * win[0][2]
                                + wa.w * win[1][0] + wb.x * win[1][1] + wb.y * win[1][2]
                                + wb.z * win[2][0] + wb.w * win[2][1] + w8 * win[2][2];
                float h1 = bias + wa.x * win[0][1] + wa.y * win[0][2] + wa.z * win[0][3]
                                + wa.w * win[1][1] + wb.x * win[1][2] + wb.y * win[1][3]
                                + wb.z * win[2][1] + wb.w * win[2][2] + w8 * win[2][3];
                const float cv = cas[c];
                h0 = fmaxf(h0, 0.f) * cv * sa0;
                h1 = fmaxf(h1, 0.f) * cv * sa1;
                *(__half2*)(ub + (size_t)c * HW) = __floats2half2_rn(h0, h1);
            }
        }
    }
}

// ---------------------------------------------------------------------------
// K4: routing streaming pass over fp16 u (iters 2,3). grid (8, BB), 256 thr.
// ---------------------------------------------------------------------------
__global__ void k_route() {
    __shared__ float gs[16];
    __shared__ float red[8][8];
    const int chunk = blockIdx.x, b = blockIdx.y, tid = threadIdx.x;
    if (tid < 16) gs[tid] = d_g[b * 16 + tid];
    __syncthreads();
    float gd[8];
#pragma unroll
    for (int k = 0; k < 8; k++) gd[k] = gs[k] - gs[8 + k];

    float a0[8];
#pragma unroll
    for (int k = 0; k < 8; k++) a0[k] = 0.f;

    const __half* up = d_u + (size_t)b * CC * HW;
    const int n0 = chunk * (NIN / 8), n1 = n0 + (NIN / 8);
    for (int n = n0 + tid; n < n1; n += 256) {
        const uint4 raw = *(const uint4*)(up + (size_t)n * 8);
        const __half2* h2 = (const __half2*)&raw;
        float u[8];
        float2 f;
        f = __half22float2(h2[0]); u[0] = f.x; u[1] = f.y;
        f = __half22float2(h2[1]); u[2] = f.x; u[3] = f.y;
        f = __half22float2(h2[2]); u[4] = f.x; u[5] = f.y;
        f = __half22float2(h2[3]); u[6] = f.x; u[7] = f.y;
        float d = 0.f;
#pragma unroll
        for (int k = 0; k < 8; k++) d += u[k] * gd[k];
        const float c0 = 1.f / (1.f + __expf(-d));
#pragma unroll
        for (int k = 0; k < 8; k++) a0[k] += c0 * u[k];
    }
    const int warp = tid >> 5, lane = tid & 31;
#pragma unroll
    for (int k = 0; k < 8; k++) {
#pragma unroll
        for (int off = 16; off; off >>= 1)
            a0[k] += __shfl_down_sync(0xffffffffu, a0[k], off);
    }
    if (lane == 0) {
#pragma unroll
        for (int k = 0; k < 8; k++) red[warp][k] = a0[k];
    }
    __syncthreads();
    if (tid < 8) {
        float s = 0.f;
#pragma unroll
        for (int w = 0; w < 8; w++) s += red[w][tid];
        d_psc[(chunk * BB + b) * 8 + tid] = s;
    }
}

// ---------------------------------------------------------------------------
// K5: routing update. MODE 0: iter1 (c=0.5 shortcut, sets S and g).
//     MODE 1: mid iter (g += W^T v). MODE 2: final (lengths).
// grid BB, 32 threads.
// ---------------------------------------------------------------------------
template <int MODE>
__global__ void k_upd(const float* __restrict__ W, float* __restrict__ out) {
    __shared__ float sc[16], ss[32], vs[32];
    const int b = blockIdx.x, tid = threadIdx.x;

    if (tid < 8) {
        if (MODE == 0) {
            float S = 0.f;
#pragma unroll
            for (int t = 0; t < NTF; t++) S += d_pu[(t * BB + b) * 8 + tid];
            d_S[b * 8 + tid] = S;
            sc[tid] = 0.5f * S;
            sc[8 + tid] = 0.5f * S;
        } else {
            float a = 0.f;
#pragma unroll
            for (int ch = 0; ch < 8; ch++) a += d_psc[(ch * BB + b) * 8 + tid];
            sc[tid] = a;
            sc[8 + tid] = d_S[b * 8 + tid] - a;
        }
    }
    __syncwarp();

    const int j = tid >> 4;
    float acc = 0.f;
#pragma unroll
    for (int k = 0; k < 8; k++) acc += sc[j * 8 + k] * W[k * 32 + tid];
    ss[tid] = acc;
    __syncwarp();

    float s2 = 1e-8f;
#pragma unroll
    for (int dd = 0; dd < 16; dd++) { const float t = ss[j * 16 + dd]; s2 += t * t; }
    const float v = (sqrtf(s2) / (1.f + s2)) * acc;
    vs[tid] = v;
    __syncwarp();

    if (MODE == 2) {
        if (tid < 2) {
            float l2 = 1e-8f;
#pragma unroll
            for (int dd = 0; dd < 16; dd++) { const float t = vs[tid * 16 + dd]; l2 += t * t; }
            out[b * 2 + tid] = sqrtf(l2);
        }
    } else {
        if (tid < 16) {
            const int jj = tid >> 3, k = tid & 7;
            float a = 0.f;
#pragma unroll
            for (int dd = 0; dd < 16; dd++) a += vs[jj * 16 + dd] * W[k * 32 + jj * 16 + dd];
            if (MODE == 0) d_g[b * 16 + tid] = a;
            else d_g[b * 16 + tid] += a;
        }
    }
}

// ---------------------------------------------------------------------------
extern "C" void kernel_launch(void* const* d_in, const int* in_sizes, int n_in,
                              void* d_out, int out_size) {
    const float* x      = (const float*)d_in[0];
    const float* conv_w = (const float*)d_in[1];
    const float* conv_b = (const float*)d_in[2];
    const float* ca_w1  = (const float*)d_in[3];
    const float* ca_w2  = (const float*)d_in[4];
    const float* sa_w   = (const float*)d_in[5];
    const float* caps_W = (const float*)d_in[6];
    float* out = (float*)d_out;

    k_stats<<<dim3(32, BB), 256>>>(x, conv_w, conv_b);
    k_ca<<<BB, 64>>>(ca_w1, ca_w2);
    k_fuse<<<dim3(NTF, BB), 256>>>(x, conv_w, conv_b, sa_w);
    k_upd<0><<<BB, 32>>>(caps_W, out);
    k_route<<<dim3(8, BB), 256>>>();
    k_upd<1><<<BB, 32>>>(caps_W, out);
    k_route<<<dim3(8, BB), 256>>>();
    k_upd<2><<<BB, 32>>>(caps_W, out);
}

// round 4
// speedup vs baseline: 1.4899x; 1.0904x over previous
#include <cuda_runtime.h>
#include <cuda_fp16.h>
#include <math.h>

#define HH 134
#define WW 20
#define HW 2680
#define CC 64
#define BB 128
#define NIN 21440        // CC*HW/8 groups per batch
#define NT_S 4
#define RT_S 34
#define NTF 8
#define RTF 17
#define NHALO 23         // RTF + 6
#define HSS 460          // NHALO * WW (halfs per channel in smem h tile)

// ---- scratch (static device globals) ----
__device__ __half d_u[(size_t)BB * CC * HW];   // u = h*ca*sa, fp16, 43.9 MB
__device__ float d_psum[NT_S * BB * CC];
__device__ float d_pmax[NT_S * BB * CC];
__device__ float d_pu[NTF * BB * 8];           // partials of S[k] = Sum_n u[k]
__device__ float d_pscA[8 * BB * 8];           // route pass A partials
__device__ float d_pscB[8 * BB * 8];           // route pass B partials

// ---------------------------------------------------------------------------
// K1: conv+relu stats only (per-(b,c) sum/max). grid (32,BB) = (cg*4+tile, b)
// ---------------------------------------------------------------------------
__global__ void k_stats(const float* __restrict__ x,
                        const float* __restrict__ cw,
                        const float* __restrict__ cb) {
    const int cg = blockIdx.x >> 2, tile = blockIdx.x & 3, b = blockIdx.y;
    const int tid = threadIdx.x;
    const int r0 = tile * RT_S, nr = min(RT_S, HH - r0);
    const int lr0 = max(r0 - 1, 0), lr1 = min(r0 + nr + 1, HH), nl = lr1 - lr0;

    __shared__ float xs[(RT_S + 2) * WW];
    __shared__ float wsh[80];
    __shared__ float red[8 * 16];

    for (int i = tid; i < nl * WW; i += 256) xs[i] = x[(size_t)b * HW + lr0 * WW + i];
    if (tid < 72) wsh[tid] = cw[cg * 72 + tid];
    if (tid >= 72 && tid < 80) wsh[tid] = cb[cg * 8 + tid - 72];
    __syncthreads();

    float wr[8][9], bsr[8];
#pragma unroll
    for (int c = 0; c < 8; c++) {
#pragma unroll
        for (int i = 0; i < 9; i++) wr[c][i] = wsh[c * 9 + i];
        bsr[c] = wsh[72 + c];
    }
    float sum[8], mx[8];
#pragma unroll
    for (int c = 0; c < 8; c++) { sum[c] = 0.f; mx[c] = 0.f; }

    for (int p = tid; p < nr * WW; p += 256) {
        const int hh = r0 + p / WW, ww = p - (p / WW) * WW;
        float win[9];
#pragma unroll
        for (int kh = 0; kh < 3; kh++) {
            const int ih = hh + kh - 1;
            const bool vr = (unsigned)ih < HH;
            const int lrow = ih - lr0;
#pragma unroll
            for (int kw = 0; kw < 3; kw++) {
                const int iw = ww + kw - 1;
                win[kh * 3 + kw] = (vr && (unsigned)iw < WW) ? xs[lrow * WW + iw] : 0.f;
            }
        }
#pragma unroll
        for (int c = 0; c < 8; c++) {
            float acc = bsr[c];
#pragma unroll
            for (int i = 0; i < 9; i++) acc += win[i] * wr[c][i];
            acc = fmaxf(acc, 0.f);
            sum[c] += acc;
            mx[c] = fmaxf(mx[c], acc);
        }
    }
    const int warp = tid >> 5, lane = tid & 31;
#pragma unroll
    for (int c = 0; c < 8; c++) {
#pragma unroll
        for (int off = 16; off; off >>= 1) {
            sum[c] += __shfl_down_sync(0xffffffffu, sum[c], off);
            mx[c] = fmaxf(mx[c], __shfl_down_sync(0xffffffffu, mx[c], off));
        }
    }
    if (lane == 0) {
#pragma unroll
        for (int c = 0; c < 8; c++) { red[warp * 16 + c] = sum[c]; red[warp * 16 + 8 + c] = mx[c]; }
    }
    __syncthreads();
    if (tid < 8) {
        float s = 0.f;
#pragma unroll
        for (int w = 0; w < 8; w++) s += red[w * 16 + tid];
        d_psum[(tile * BB + b) * CC + cg * 8 + tid] = s;
    } else if (tid < 16) {
        float m = 0.f;
#pragma unroll
        for (int w = 0; w < 8; w++) m = fmaxf(m, red[w * 16 + tid]);  // slots 8..15 = max
        d_pmax[(tile * BB + b) * CC + cg * 8 + tid - 8] = m;
    }
}

// ---------------------------------------------------------------------------
// K2: fused ca-MLP (inline, per block) + spatial attention + u (fp16) + S partials.
// Conv computed ONCE per tile into smem fp16 (ca-weighted). grid (NTF,BB), 256 thr.
// Dynamic smem: h tile, 64*HSS halfs = 57.5 KB.
// ---------------------------------------------------------------------------
__global__ void k_fuse(const float* __restrict__ x,
                       const float* __restrict__ cw,
                       const float* __restrict__ cb,
                       const float* __restrict__ sw,
                       const float* __restrict__ w1,
                       const float* __restrict__ w2) {
    extern __shared__ __half hs[];                // [CC][NHALO*WW] h*ca, fp16
    __shared__ __align__(16) float wsh[CC * 12];
    __shared__ float cbs[CC], cas[CC], ws[98];
    __shared__ float avg_s[CC], mx_s[CC], hid_s[8];
    __shared__ float xs[25 * WW];
    __shared__ float spm[NHALO * WW], spx[NHALO * WW];
    __shared__ float sa_s[RTF * WW];
    __shared__ float red[8][8];

    const int tile = blockIdx.x, b = blockIdx.y, tid = threadIdx.x;
    const int r0 = tile * RTF, nr = min(RTF, HH - r0);
    const int hs0 = max(r0 - 3, 0), hs1 = min(r0 + nr + 3, HH), nhs = hs1 - hs0;
    const int lx0 = max(hs0 - 1, 0), lx1 = min(hs1 + 1, HH), nlx = lx1 - lx0;

    // stage 0: loads + channel-attention stats (all independent)
    for (int i = tid; i < CC * 12; i += 256) {
        const int c = i / 12, q = i - c * 12;
        wsh[i] = (q < 9) ? cw[c * 9 + q] : 0.f;
    }
    if (tid < CC) {
        cbs[tid] = cb[tid];
        float s = 0.f, m = 0.f;
#pragma unroll
        for (int t = 0; t < NT_S; t++) {
            s += d_psum[(t * BB + b) * CC + tid];
            m = fmaxf(m, d_pmax[(t * BB + b) * CC + tid]);
        }
        avg_s[tid] = s * (1.f / (float)HW);
        mx_s[tid] = m;
    }
    if (tid >= 64 && tid < 64 + 98) ws[tid - 64] = sw[tid - 64];
    for (int i = tid; i < nlx * WW; i += 256) xs[i] = x[(size_t)b * HW + lx0 * WW + i];
    __syncthreads();

    // stage 1: ca MLP hidden
    if (tid < 8) {
        const int i = tid & 3;
        const float* v = (tid < 4) ? avg_s : mx_s;
        float a = 0.f;
        for (int c = 0; c < CC; c++) a += v[c] * w1[i * CC + c];
        hid_s[tid] = fmaxf(a, 0.f);
    }
    __syncthreads();
    if (tid < CC) {
        float o = 0.f;
#pragma unroll
        for (int i = 0; i < 4; i++) o += (hid_s[i] + hid_s[4 + i]) * w2[tid * 4 + i];
        cas[tid] = 1.f / (1.f + __expf(-o));
    }
    __syncthreads();

    // stage A: conv once over halo rows -> hs (fp16, ca-weighted) + spm/spx
    {
        const int pairs = nhs * 10;
        if (tid < pairs) {
            const int lrow = tid / 10, col2 = (tid - lrow * 10) * 2;
            const int row = hs0 + lrow;
            float win[3][4];
#pragma unroll
            for (int r = 0; r < 3; r++) {
                const int ih = row - 1 + r;
                const bool vr = (ih >= lx0) && (ih < lx1);
                const int lr = ih - lx0;
#pragma unroll
                for (int q = 0; q < 4; q++) {
                    const int iw = col2 - 1 + q;
                    win[r][q] = (vr && (unsigned)iw < WW) ? xs[lr * WW + iw] : 0.f;
                }
            }
            float s0 = 0.f, s1 = 0.f, m0 = -1e30f, m1 = -1e30f;
#pragma unroll 4
            for (int c = 0; c < CC; c++) {
                const float4 wa = *(const float4*)&wsh[c * 12];
                const float4 wb = *(const float4*)&wsh[c * 12 + 4];
                const float w8 = wsh[c * 12 + 8];
                const float bias = cbs[c];
                float h0 = bias + wa.x * win[0][0] + wa.y * win[0][1] + wa.z * win[0][2]
                                + wa.w * win[1][0] + wb.x * win[1][1] + wb.y * win[1][2]
                                + wb.z * win[2][0] + wb.w * win[2][1] + w8 * win[2][2];
                float h1 = bias + wa.x * win[0][1] + wa.y * win[0][2] + wa.z * win[0][3]
                                + wa.w * win[1][1] + wb.x * win[1][2] + wb.y * win[1][3]
                                + wb.z * win[2][1] + wb.w * win[2][2] + w8 * win[2][3];
                const float cv = cas[c];
                h0 = fmaxf(h0, 0.f) * cv;
                h1 = fmaxf(h1, 0.f) * cv;
                *(__half2*)&hs[c * HSS + lrow * WW + col2] = __floats2half2_rn(h0, h1);
                s0 += h0; s1 += h1;
                m0 = fmaxf(m0, h0); m1 = fmaxf(m1, h1);
            }
            const int lp = lrow * WW + col2;
            spm[lp] = s0 * (1.f / (float)CC);
            spm[lp + 1] = s1 * (1.f / (float)CC);
            spx[lp] = m0;
            spx[lp + 1] = m1;
        }
    }
    __syncthreads();

    // stage B: 7x7 conv -> sa; accumulate S[k] partials
    float ps[8];
#pragma unroll
    for (int k = 0; k < 8; k++) ps[k] = 0.f;
    for (int p = tid; p < nr * WW; p += 256) {
        const int hh = r0 + p / WW, ww = p - (p / WW) * WW;
        float acc = 0.f;
#pragma unroll
        for (int kh = 0; kh < 7; kh++) {
            const int ih = hh + kh - 3;
            if ((unsigned)ih >= HH) continue;
            const int lrow = ih - hs0;
#pragma unroll
            for (int kw = 0; kw < 7; kw++) {
                const int iw = ww + kw - 3;
                if ((unsigned)iw >= WW) continue;
                const int q = lrow * WW + iw;
                acc += spm[q] * ws[kh * 7 + kw] + spx[q] * ws[49 + kh * 7 + kw];
            }
        }
        const float sa = 1.f / (1.f + __expf(-acc));
        sa_s[p] = sa;
        const int k = (r0 * WW + p) & 7;
        ps[k] += (float)CC * spm[(hh - hs0) * WW + ww] * sa;
    }
    const int warp = tid >> 5, lane = tid & 31;
#pragma unroll
    for (int k = 0; k < 8; k++) {
#pragma unroll
        for (int off = 16; off; off >>= 1)
            ps[k] += __shfl_down_sync(0xffffffffu, ps[k], off);
    }
    if (lane == 0) {
#pragma unroll
        for (int k = 0; k < 8; k++) red[warp][k] = ps[k];
    }
    __syncthreads();
    if (tid < 8) {
        float s = 0.f;
#pragma unroll
        for (int w = 0; w < 8; w++) s += red[w][tid];
        d_pu[(tile * BB + b) * 8 + tid] = s;
    }

    // stage C: u = hs * sa -> global fp16 (no conv recompute)
    {
        const int pairs = nr * 10;
        if (tid < pairs) {
            const int lrow = tid / 10, col2 = (tid - lrow * 10) * 2;
            const int row = r0 + lrow;
            const int hrow = row - hs0;
            const float sa0 = sa_s[lrow * WW + col2];
            const float sa1 = sa_s[lrow * WW + col2 + 1];
            const __half2 sav = __floats2half2_rn(sa0, sa1);
            __half* ub = d_u + (size_t)b * CC * HW + row * WW + col2;
#pragma unroll 8
            for (int c = 0; c < CC; c++) {
                const __half2 hv = *(const __half2*)&hs[c * HSS + hrow * WW + col2];
                *(__half2*)(ub + (size_t)c * HW) = __hmul2(hv, sav);
            }
        }
    }
}

// ---------------------------------------------------------------------------
// inline routing update chain: sc[16] -> s -> squash -> v -> g (warp-wide)
// ---------------------------------------------------------------------------
__device__ __forceinline__ void upd_chain(const float* __restrict__ W,
                                          const float* sc, float* vs,
                                          float* g, bool add, int lane) {
    const int j = lane >> 4;
    float acc = 0.f;
#pragma unroll
    for (int k = 0; k < 8; k++) acc += sc[j * 8 + k] * W[k * 32 + lane];
    float s2 = acc * acc;
#pragma unroll
    for (int off = 8; off; off >>= 1) s2 += __shfl_xor_sync(0xffffffffu, s2, off, 16);
    s2 += 1e-8f;
    const float v = (sqrtf(s2) / (1.f + s2)) * acc;
    vs[lane] = v;
    __syncwarp();
    if (lane < 16) {
        const int jj = lane >> 3, k = lane & 7;
        float a = 0.f;
#pragma unroll
        for (int dd = 0; dd < 16; dd++) a += vs[jj * 16 + dd] * W[k * 32 + jj * 16 + dd];
        g[lane] = add ? (g[lane] + a) : a;
    }
    __syncwarp();
}

// ---------------------------------------------------------------------------
// K3: routing streaming pass. PASS 0: g1 from S. PASS 1: g2 = g1 + dW(pscA).
// grid (8, BB), 256 threads. Writes pscA / pscB.
// ---------------------------------------------------------------------------
template <int PASS>
__global__ void k_route(const float* __restrict__ W) {
    __shared__ float Ssh[8], ash[8], sc[16], vs[32], g[16];
    __shared__ float red[8][8];
    const int chunk = blockIdx.x, b = blockIdx.y, tid = threadIdx.x;

    if (tid < 32) {
        if (tid < 8) {
            float S = 0.f;
#pragma unroll
            for (int t = 0; t < NTF; t++) S += d_pu[(t * BB + b) * 8 + tid];
            Ssh[tid] = S;
        }
        __syncwarp();
        if (tid < 16) sc[tid] = 0.5f * Ssh[tid & 7];
        __syncwarp();
        upd_chain(W, sc, vs, g, false, tid);       // g1
        if (PASS == 1) {
            if (tid < 8) {
                float a = 0.f;
#pragma unroll
                for (int ch = 0; ch < 8; ch++) a += d_pscA[(ch * BB + b) * 8 + tid];
                ash[tid] = a;
            }
            __syncwarp();
            if (tid < 16) sc[tid] = (tid < 8) ? ash[tid] : (Ssh[tid - 8] - ash[tid - 8]);
            __syncwarp();
            upd_chain(W, sc, vs, g, true, tid);    // g2
        }
    }
    __syncthreads();

    float gd[8];
#pragma unroll
    for (int k = 0; k < 8; k++) gd[k] = g[k] - g[8 + k];

    float a0[8];
#pragma unroll
    for (int k = 0; k < 8; k++) a0[k] = 0.f;

    const __half* up = d_u + (size_t)b * CC * HW;
    const int n0 = chunk * (NIN / 8), n1 = n0 + (NIN / 8);

    auto body = [&](int n) {
        const uint4 raw = *(const uint4*)(up + (size_t)n * 8);
        const __half2* h2 = (const __half2*)&raw;
        float u[8];
        float2 f;
        f = __half22float2(h2[0]); u[0] = f.x; u[1] = f.y;
        f = __half22float2(h2[1]); u[2] = f.x; u[3] = f.y;
        f = __half22float2(h2[2]); u[4] = f.x; u[5] = f.y;
        f = __half22float2(h2[3]); u[6] = f.x; u[7] = f.y;
        float d = 0.f;
#pragma unroll
        for (int k = 0; k < 8; k++) d += u[k] * gd[k];
        const float c0 = 1.f / (1.f + __expf(-d));
#pragma unroll
        for (int k = 0; k < 8; k++) a0[k] += c0 * u[k];
    };

    int n = n0 + tid;
    for (; n + 256 < n1; n += 512) { body(n); body(n + 256); }
    for (; n < n1; n += 256) body(n);

    const int warp = tid >> 5, lane = tid & 31;
#pragma unroll
    for (int k = 0; k < 8; k++) {
#pragma unroll
        for (int off = 16; off; off >>= 1)
            a0[k] += __shfl_down_sync(0xffffffffu, a0[k], off);
    }
    if (lane == 0) {
#pragma unroll
        for (int k = 0; k < 8; k++) red[warp][k] = a0[k];
    }
    __syncthreads();
    if (tid < 8) {
        float s = 0.f;
#pragma unroll
        for (int w = 0; w < 8; w++) s += red[w][tid];
        float* psc = PASS ? d_pscB : d_pscA;
        psc[(chunk * BB + b) * 8 + tid] = s;
    }
}

// ---------------------------------------------------------------------------
// K4: final lengths from pscB. grid BB, 32 threads.
// ---------------------------------------------------------------------------
__global__ void k_final(const float* __restrict__ W, float* __restrict__ out) {
    __shared__ float Ssh[8], ash[8], sc[16];
    const int b = blockIdx.x, lane = threadIdx.x;
    if (lane < 8) {
        float S = 0.f, a = 0.f;
#pragma unroll
        for (int t = 0; t < NTF; t++) S += d_pu[(t * BB + b) * 8 + lane];
#pragma unroll
        for (int ch = 0; ch < 8; ch++) a += d_pscB[(ch * BB + b) * 8 + lane];
        Ssh[lane] = S;
        ash[lane] = a;
    }
    __syncwarp();
    if (lane < 16) sc[lane] = (lane < 8) ? ash[lane] : (Ssh[lane - 8] - ash[lane - 8]);
    __syncwarp();
    const int j = lane >> 4;
    float acc = 0.f;
#pragma unroll
    for (int k = 0; k < 8; k++) acc += sc[j * 8 + k] * W[k * 32 + lane];
    float s2 = acc * acc;
#pragma unroll
    for (int off = 8; off; off >>= 1) s2 += __shfl_xor_sync(0xffffffffu, s2, off, 16);
    s2 += 1e-8f;
    const float v = (sqrtf(s2) / (1.f + s2)) * acc;
    float l2 = v * v;
#pragma unroll
    for (int off = 8; off; off >>= 1) l2 += __shfl_xor_sync(0xffffffffu, l2, off, 16);
    if ((lane & 15) == 0) out[b * 2 + j] = sqrtf(l2 + 1e-8f);
}

// ---------------------------------------------------------------------------
extern "C" void kernel_launch(void* const* d_in, const int* in_sizes, int n_in,
                              void* d_out, int out_size) {
    const float* x      = (const float*)d_in[0];
    const float* conv_w = (const float*)d_in[1];
    const float* conv_b = (const float*)d_in[2];
    const float* ca_w1  = (const float*)d_in[3];
    const float* ca_w2  = (const float*)d_in[4];
    const float* sa_w   = (const float*)d_in[5];
    const float* caps_W = (const float*)d_in[6];
    float* out = (float*)d_out;

    const int hs_bytes = CC * HSS * sizeof(__half);  // 58880
    cudaFuncSetAttribute(k_fuse, cudaFuncAttributeMaxDynamicSharedMemorySize, hs_bytes);

    k_stats<<<dim3(32, BB), 256>>>(x, conv_w, conv_b);
    k_fuse<<<dim3(NTF, BB), 256, hs_bytes>>>(x, conv_w, conv_b, sa_w, ca_w1, ca_w2);
    k_route<0><<<dim3(8, BB), 256>>>(caps_W);
    k_route<1><<<dim3(8, BB), 256>>>(caps_W);
    k_final<<<BB, 32>>>(caps_W, out);
}